// round 3
// baseline (speedup 1.0000x reference)
#include <cuda_runtime.h>
#include <math.h>

#define NB   8192
#define ND   256
#define NPOS 8
#define NT   64      // number of 128-wide column tiles

// ---------------- device scratch (no allocations allowed) ----------------
__device__ float g_z[NB * ND];          // normalized embeddings
__device__ float g_pSpd[NT * NB];       // per (colTile,row): sum e^s over pos+diag
__device__ float g_pSneg[NT * NB];      // per (colTile,row): sum e^s over neg
__device__ float g_pTneg[NT * NB];      // per (colTile,row): sum s*e^s over neg
__device__ float g_pos_s[NB * NPOS];    // s at positive pairs
__device__ float g_lse[NB];
__device__ float g_inv_temp;
__device__ unsigned g_negmin_e, g_negmax_e, g_pvmin_e, g_pvmax_e;

// monotone float<->uint encoding so atomicMin/Max on unsigned give float min/max
__device__ __forceinline__ unsigned encf(float f) {
    unsigned u = __float_as_uint(f);
    return (u & 0x80000000u) ? ~u : (u | 0x80000000u);
}
__device__ __forceinline__ float decf(unsigned e) {
    return __uint_as_float((e & 0x80000000u) ? (e & 0x7FFFFFFFu) | ((e >> 31) ? 0u : 0u) : 0u);
}
// (decf above is wrong-prone; use explicit inverse)
__device__ __forceinline__ float decf2(unsigned e) {
    unsigned u = (e & 0x80000000u) ? (e ^ 0x80000000u) : ~e;
    return __uint_as_float(u);
}

// ---------------- kernels ----------------
__global__ void k_init(const float* __restrict__ temp) {
    float t = temp[0];
    float sp = log1pf(expf(t));       // softplus
    g_inv_temp = 1.0f / sp;
    g_negmin_e = 0xFFFFFFFFu;
    g_negmax_e = 0u;
    g_pvmin_e  = 0xFFFFFFFFu;
    g_pvmax_e  = 0u;
}

__global__ void k_norm(const float* __restrict__ emb) {
    int row = blockIdx.x;
    int t   = threadIdx.x;                 // 256 threads, one element each
    float x = emb[row * ND + t];
    float s = x * x;
    #pragma unroll
    for (int o = 16; o > 0; o >>= 1) s += __shfl_xor_sync(0xFFFFFFFFu, s, o);
    __shared__ float ws[8];
    if ((t & 31) == 0) ws[t >> 5] = s;
    __syncthreads();
    float tot = 0.0f;
    #pragma unroll
    for (int i = 0; i < 8; i++) tot += ws[i];
    float norm = sqrtf(tot);
    float dn = fmaxf(norm, 1e-12f);
    g_z[row * ND + t] = x / dn;
}

__global__ void k_pvminmax(const float* __restrict__ pv) {
    int i = blockIdx.x * blockDim.x + threadIdx.x;    // 65536 total
    float v = pv[i];
    float mn = v, mx = v;
    #pragma unroll
    for (int o = 16; o > 0; o >>= 1) {
        mn = fminf(mn, __shfl_xor_sync(0xFFFFFFFFu, mn, o));
        mx = fmaxf(mx, __shfl_xor_sync(0xFFFFFFFFu, mx, o));
    }
    if ((threadIdx.x & 31) == 0) {
        atomicMin(&g_pvmin_e, encf(mn));
        atomicMax(&g_pvmax_e, encf(mx));
    }
}

// 128x128 tile of sim per block; fused exp + masked reductions epilogue.
__global__ void __launch_bounds__(256, 2) k_gemm() {
    const int bm = blockIdx.y, bn = blockIdx.x;
    const int tid = threadIdx.x;
    const int tx = tid & 15, ty = tid >> 4;
    const int row0 = bm * 128, col0 = bn * 128;

    __shared__ float As[8][132];
    __shared__ float Bs[8][132];

    float acc[8][8];
    #pragma unroll
    for (int i = 0; i < 8; i++)
        #pragma unroll
        for (int j = 0; j < 8; j++) acc[i][j] = 0.0f;

    const int lr = tid >> 1;          // row within tile this thread loads
    const int kh = (tid & 1) * 4;     // k-half offset

    for (int k0 = 0; k0 < ND; k0 += 8) {
        float4 a = *reinterpret_cast<const float4*>(&g_z[(row0 + lr) * ND + k0 + kh]);
        float4 b = *reinterpret_cast<const float4*>(&g_z[(col0 + lr) * ND + k0 + kh]);
        As[kh + 0][lr] = a.x; As[kh + 1][lr] = a.y; As[kh + 2][lr] = a.z; As[kh + 3][lr] = a.w;
        Bs[kh + 0][lr] = b.x; Bs[kh + 1][lr] = b.y; Bs[kh + 2][lr] = b.z; Bs[kh + 3][lr] = b.w;
        __syncthreads();
        #pragma unroll
        for (int kk = 0; kk < 8; kk++) {
            float ra[8], rb[8];
            #pragma unroll
            for (int i = 0; i < 8; i++) ra[i] = As[kk][ty * 8 + i];
            #pragma unroll
            for (int j = 0; j < 8; j++) rb[j] = Bs[kk][tx * 8 + j];
            #pragma unroll
            for (int i = 0; i < 8; i++)
                #pragma unroll
                for (int j = 0; j < 8; j++) acc[i][j] = fmaf(ra[i], rb[j], acc[i][j]);
        }
        __syncthreads();
    }

    // ---- epilogue: s = (dot-1)*inv_temp (shift-invariant, diag-dominant) ----
    const float it = g_inv_temp;
    float spd[8], sng[8], tng[8];
    #pragma unroll
    for (int i = 0; i < 8; i++) { spd[i] = 0.0f; sng[i] = 0.0f; tng[i] = 0.0f; }
    float lmin = 1e30f, lmax = -1e30f;

    #pragma unroll
    for (int i = 0; i < 8; i++) {
        int gi = row0 + ty * 8 + i;
        #pragma unroll
        for (int j = 0; j < 8; j++) {
            int gj = col0 + tx * 8 + j;
            float s = (acc[i][j] - 1.0f) * it;
            float e = __expf(s);
            int d = gj - gi;
            if (d < 0) d += NB;
            if (d == 0) {
                spd[i] += e;
            } else if (d <= NPOS) {
                spd[i] += e;
                g_pos_s[gi * NPOS + (d - 1)] = s;   // unique writer
            } else {
                sng[i] += e;
                tng[i] += s * e;
                lmin = fminf(lmin, s);
                lmax = fmaxf(lmax, s);
            }
        }
    }

    // reduce each row's partials across the 16 tx lanes (half-warp segments)
    #pragma unroll
    for (int i = 0; i < 8; i++) {
        float a0 = spd[i], a1 = sng[i], a2 = tng[i];
        #pragma unroll
        for (int o = 8; o > 0; o >>= 1) {
            a0 += __shfl_down_sync(0xFFFFFFFFu, a0, o, 16);
            a1 += __shfl_down_sync(0xFFFFFFFFu, a1, o, 16);
            a2 += __shfl_down_sync(0xFFFFFFFFu, a2, o, 16);
        }
        if (tx == 0) {
            int gi = row0 + ty * 8 + i;
            g_pSpd [bn * NB + gi] = a0;
            g_pSneg[bn * NB + gi] = a1;
            g_pTneg[bn * NB + gi] = a2;
        }
    }

    // global neg min/max via order-invariant encoded atomics
    #pragma unroll
    for (int o = 16; o > 0; o >>= 1) {
        lmin = fminf(lmin, __shfl_xor_sync(0xFFFFFFFFu, lmin, o));
        lmax = fmaxf(lmax, __shfl_xor_sync(0xFFFFFFFFu, lmax, o));
    }
    if ((tid & 31) == 0) {
        atomicMin(&g_negmin_e, encf(lmin));
        atomicMax(&g_negmax_e, encf(lmax));
    }
}

__global__ void k_lse() {
    int i = blockIdx.x * blockDim.x + threadIdx.x;   // 8192 rows
    float spd = 0.0f, sn = 0.0f, tn = 0.0f;
    #pragma unroll 8
    for (int t = 0; t < NT; t++) {
        spd += g_pSpd [t * NB + i];
        sn  += g_pSneg[t * NB + i];
        tn  += g_pTneg[t * NB + i];
    }
    float nmin = decf2(g_negmin_e);
    float nmax = decf2(g_negmax_e);
    float a = 1.0f / (nmax - nmin + 1e-8f);
    float b = 1.0f - nmin * a;
    g_lse[i] = logf(spd + a * tn + b * sn);
}

__global__ void k_final(const float* __restrict__ pv, float* __restrict__ out) {
    const int tid = threadIdx.x;                     // 1024 threads, 1 block
    float vmin = decf2(g_pvmin_e);
    float vmax = decf2(g_pvmax_e);
    float wmin = 1.0f - vmax;
    float wmax = 1.0f - vmin;
    float inv = 1.0f / (wmax - wmin + 1e-8f);

    float local = 0.0f;
    for (int idx = tid; idx < NB * NPOS; idx += 1024) {
        int i = idx >> 3;
        float pw = ((1.0f - pv[idx]) - wmin) * inv;
        local += (g_pos_s[idx] - g_lse[i]) * pw;
    }
    __shared__ float red[1024];
    red[tid] = local;
    __syncthreads();
    for (int s = 512; s > 0; s >>= 1) {
        if (tid < s) red[tid] += red[tid + s];
        __syncthreads();
    }
    if (tid == 0) out[0] = -red[0] * (1.0f / (float)(NB * NPOS));
}

// ---------------- launch ----------------
extern "C" void kernel_launch(void* const* d_in, const int* in_sizes, int n_in,
                              void* d_out, int out_size) {
    const float* emb  = (const float*)d_in[0];
    const float* pv   = (const float*)d_in[1];
    const float* temp = (const float*)d_in[2];
    float* out = (float*)d_out;

    k_init<<<1, 1>>>(temp);
    k_norm<<<NB, ND>>>(emb);
    k_pvminmax<<<(NB * NPOS) / 1024, 1024>>>(pv);
    dim3 grid(NT, NT);
    k_gemm<<<grid, 256>>>();
    k_lse<<<NB / 256, 256>>>();
    k_final<<<1, 1024>>>(pv, out);
}